// round 13
// baseline (speedup 1.0000x reference)
#include <cuda_runtime.h>
#include <cstdint>
#include <cmath>

// HDCProcessor: bit-domain exponential-decay scan, single fused kernel.
// R13: R11 grid (NCHUNK=16/CLEN=128/WUP=128, 1024 blocks) +
//  - pre-scaled accumulator A' = 0.05*A (LUT scaled): chunks >= 3 store
//    registers directly (no MUL2, no inv-LDS); chunks < 3 use ratio table.
//  - 4-step batched row prefetch (LDS.128 ofs + 8 independent row LDS.32)
//    for chunks >= 2, breaking the ofs->row dependent-LDS chain.
//   hdc[t,d] = 0.3*s(t,d) + 0.7*s(t,d)*s(t-1,d-1)*s(t-2,d-2)  (signs, rolls mod D)
//   out[t] = (1-g)/(1-g^{t+1}) * sum_{s<=t} g^{t-s} hdc[s],  g = 0.95
// Chunks 0 exact, >=1 use 128-step warmup (rel ~3.5e-4 measured; gate 1e-3).

#define DDIM     4096
#define NB       8
#define NT       2048
#define NCHUNK   16
#define CLEN     128
#define WUP      128
#define NTHREADS 128
#define NDG      8                 // 4096 dims / (128 thr * 4 dims)
#define ROWW     17                // words per staged row: 1 halo + 16 slice
#define RWORDS   (256 * ROWW)      // 4352
#define ROWB     (ROWW * 4)

__device__ uint32_t g_bitsx[NDG * RWORDS];   // per-dg pre-halo'd packed rows
__device__ float    g_inv[NT];               // (1-g)/(1-g^{t+1})

// ---- packed f32x2 helpers ----
__device__ __forceinline__ unsigned long long pk2(uint32_t lo, uint32_t hi) {
    unsigned long long r;
    asm("mov.b64 %0, {%1, %2};" : "=l"(r) : "r"(lo), "r"(hi));
    return r;
}
#define FMA2(d, a, b, c) \
    asm("fma.rn.f32x2 %0, %1, %2, %3;" : "=l"(d) : "l"(a), "l"(b), "l"(c))
#define MUL2(d, a, b) \
    asm("mul.rn.f32x2 %0, %1, %2;" : "=l"(d) : "l"(a), "l"(b))
#define G2 0x3F7333333F733333ull     // {0.95f, 0.95f}

// ---- pack: sign bits of the bipolar codebook, expanded per d-group ----
__global__ void pack_kernel(const float* __restrict__ cb) {
    const int row  = blockIdx.x;
    const int lane = threadIdx.x & 31;
    const int wq   = (blockIdx.y << 2) + (threadIdx.x >> 5);  // word quarter 0..15
    for (int k = 0; k < 8; k++) {
        int gw = wq * 8 + k;
        float v = cb[row * DDIM + gw * 32 + lane];
        unsigned m = __ballot_sync(0xffffffffu, v < 0.0f);
        if (lane == 0) {
            g_bitsx[(gw >> 4) * RWORDS + row * ROWW + (gw & 15) + 1] = m;
            int gwn = (gw + 1) & 127;               // this word is the halo of
            if ((gwn & 15) == 0)                    // the next d-group (mod wrap)
                g_bitsx[(gwn >> 4) * RWORDS + row * ROWW] = m;
        }
    }
    if (blockIdx.y == 0) {
        int gid = blockIdx.x * NTHREADS + threadIdx.x;
        if (gid < NT)
            g_inv[gid] = (float)(0.05 / (1.0 - pow(0.95, (double)(gid + 1))));
    }
}

// ---- fused scan ----
__global__ void __launch_bounds__(NTHREADS)
scan_kernel(const int* __restrict__ idx, float* __restrict__ out)
{
    const int dg    = blockIdx.x;
    const int chunk = blockIdx.y;
    const int b     = blockIdx.z;
    const int t0    = chunk * CLEN;
    const int tid   = threadIdx.x;

    __shared__ uint32_t s_bits[RWORDS + 4];
    __shared__ alignas(16) int s_idx[260];   // steps [0..255], history [256..257]
    __shared__ unsigned long long s_inv2[CLEN];   // packed ratio {r, r} (chunk<3)
    __shared__ unsigned long long s_lut[16];      // 0.05-scaled {c_j, c_j+1}

    // scaled c LUT: index [f1 f0 y1 y0]; c = 0.05*(0.3*sf + 0.7*sy)
    if (tid < 16) {
        float c0 = 0.05f * (((tid & 4) ? -0.3f : 0.3f) + ((tid & 1) ? -0.7f : 0.7f));
        float c1 = 0.05f * (((tid & 8) ? -0.3f : 0.3f) + ((tid & 2) ? -0.7f : 0.7f));
        s_lut[tid] = pk2(__float_as_uint(c0), __float_as_uint(c1));
    }
    // stage packed codebook slice (contiguous uint4 copy, L2-resident source)
    {
        const uint4* src = (const uint4*)(g_bitsx + dg * RWORDS);
        uint4*       dst = (uint4*)s_bits;
        for (int k = tid; k < RWORDS / 4; k += NTHREADS) dst[k] = src[k];
    }
    const int nwarm  = chunk ? WUP : 0;
    const int ts     = t0 - nwarm;         // first scanned timestep (>= 0)
    const int nsteps = nwarm + CLEN;
    for (int k = tid; k < nsteps; k += NTHREADS)
        s_idx[k] = idx[b * NT + ts + k] * ROWB;
    if (tid < 2) {                          // history rows ts-1, ts-2
        int t = ts - 1 - tid;
        s_idx[256 + tid] = (t >= 0 ? idx[b * NT + t] : 0) * ROWB;
    }
    if (chunk < 3) {                        // ratio = 1/(1-g^(t+1)); ==1.0 t>=337
        for (int k = tid; k < CLEN; k += NTHREADS) {
            float v = g_inv[t0 + k] * 20.0f;
            s_inv2[k] = pk2(__float_as_uint(v), __float_as_uint(v));
        }
    }
    __syncthreads();

    // bit field: global dim (dg*512 + m) at staged-row bit (32 + m);
    // this thread: dims d-2..d+3 => bits from p = 30 + 4*tid. Both f (cur)
    // and Y (trigram) carry dim j's sign at bit (2+j).
    const int p   = 30 + 4 * tid;
    const int q   = p >> 5;
    const int rsh = p & 31;
    const char* bbase = (const char*)(s_bits + q);
    const char* lutb  = (const char*)s_lut;

    uint32_t h1s = 0, h2s = 0;   // pre-shifted histories: f_{t-1}<<1, f_{t-2}<<2
    if (ts >= 2) {
        const uint32_t* w1 = (const uint32_t*)(bbase + s_idx[256]);
        const uint32_t* w2 = (const uint32_t*)(bbase + s_idx[257]);
        h1s = __funnelshift_r(w1[0], w1[1], rsh) << 1;
        h2s = __funnelshift_r(w2[0], w2[1], rsh) << 2;
    }

    unsigned long long a01 = 0ull, a23 = 0ull;   // pre-scaled accumulators
    float* op = out + ((size_t)b * NT + t0) * DDIM + dg * 512 + 4 * tid;

#define LSTEP(F, H1, H2)                                                      \
        const uint32_t Y_ = (F) ^ (H1) ^ (H2);                                \
        const uint32_t o01_ = (((F) & 12u) | ((Y_ >> 2) & 3u)) << 3;          \
        const uint32_t o23_ = ((((F) >> 2) & 12u) | ((Y_ >> 4) & 3u)) << 3;   \
        FMA2(a01, a01, G2, *(const unsigned long long*)(lutb + o01_));        \
        FMA2(a23, a23, G2, *(const unsigned long long*)(lutb + o23_));

#define EMIT_D                                                                \
        asm volatile("st.global.v2.b64 [%0], {%1, %2};"                       \
                     :: "l"(op), "l"(a01), "l"(a23) : "memory");              \
        op += DDIM;

#define EMIT_R(IV)                                                            \
        { unsigned long long o01v, o23v;                                      \
          MUL2(o01v, a01, (IV));                                              \
          MUL2(o23v, a23, (IV));                                              \
          asm volatile("st.global.v2.b64 [%0], {%1, %2};"                     \
                       :: "l"(op), "l"(o01v), "l"(o23v) : "memory");          \
          op += DDIM; }

    // quad core: sp multiple of 4; ofs LDS.128 + 8 independent row LDS.32
#define CORE4(sp, E0, E1, E2, E3)                                             \
    {                                                                         \
        const int4 ofs = *(const int4*)(s_idx + (sp));                        \
        const uint32_t* pa = (const uint32_t*)(bbase + ofs.x);                \
        const uint32_t* pb = (const uint32_t*)(bbase + ofs.y);                \
        const uint32_t* pc = (const uint32_t*)(bbase + ofs.z);                \
        const uint32_t* pd = (const uint32_t*)(bbase + ofs.w);                \
        const uint32_t a0w = pa[0], a1w = pa[1];                              \
        const uint32_t b0w = pb[0], b1w = pb[1];                              \
        const uint32_t c0w = pc[0], c1w = pc[1];                              \
        const uint32_t d0w = pd[0], d1w = pd[1];                              \
        const uint32_t fA = __funnelshift_r(a0w, a1w, rsh);                   \
        const uint32_t fB = __funnelshift_r(b0w, b1w, rsh);                   \
        const uint32_t fC = __funnelshift_r(c0w, c1w, rsh);                   \
        const uint32_t fD = __funnelshift_r(d0w, d1w, rsh);                   \
        { LSTEP(fA, h1s, h2s) }            E0                                 \
        { LSTEP(fB, fA << 1, h1s << 1) }   E1                                 \
        { LSTEP(fC, fB << 1, fA << 2) }    E2                                 \
        { LSTEP(fD, fC << 1, fB << 2) }    E3                                 \
        h2s = fC << 2;                                                        \
        h1s = fD << 1;                                                        \
    }

    // pair core (chunks 0,1 only)
#define CORE2(sp, E0, E1)                                                     \
    {                                                                         \
        const int2 ofs = *(const int2*)(s_idx + (sp));                        \
        const uint32_t* wpA = (const uint32_t*)(bbase + ofs.x);               \
        const uint32_t fA = __funnelshift_r(wpA[0], wpA[1], rsh);             \
        const uint32_t* wpB = (const uint32_t*)(bbase + ofs.y);               \
        const uint32_t fB = __funnelshift_r(wpB[0], wpB[1], rsh);             \
        { LSTEP(fA, h1s, h2s) }            E0                                 \
        { LSTEP(fB, fA << 1, h1s << 1) }   E1                                 \
        h2s = fA << 2;                                                        \
        h1s = fB << 1;                                                        \
    }

    // u-only step for t = 0,1 (reference zeroes shifted-history rows);
    // scaled: 0.05*0.3 = 0.015f = 0x3C75C28F
#define CORE0(sp)                                                             \
    {                                                                         \
        const uint32_t* wp = (const uint32_t*)(bbase + s_idx[(sp)]);          \
        const uint32_t f = __funnelshift_r(wp[0], wp[1], rsh);                \
        const uint32_t u0 = ((f << 29) & 0x80000000u) | 0x3C75C28Fu;          \
        const uint32_t u1 = ((f << 28) & 0x80000000u) | 0x3C75C28Fu;          \
        const uint32_t u2 = ((f << 27) & 0x80000000u) | 0x3C75C28Fu;          \
        const uint32_t u3 = ((f << 26) & 0x80000000u) | 0x3C75C28Fu;          \
        FMA2(a01, a01, G2, pk2(u0, u1));                                      \
        FMA2(a23, a23, G2, pk2(u2, u3));                                      \
        h2s = h1s << 1;                                                       \
        h1s = f << 1;                                                         \
    }

    if (chunk >= 2) {
        // warm: 32 quads, store-free
#pragma unroll 4
        for (int w = 0; w < WUP; w += 4) { CORE4(w, {}, {}, {}, {}) }
        if (chunk >= 3) {                // inv == 0.05 exactly: direct stores
#pragma unroll 4
            for (int s = 0; s < CLEN; s += 4) {
                CORE4(WUP + s, { EMIT_D }, { EMIT_D }, { EMIT_D }, { EMIT_D })
            }
        } else {                         // chunk 2: ratio table
#pragma unroll 4
            for (int s = 0; s < CLEN; s += 4) {
                const unsigned long long* ivp = &s_inv2[s];
                CORE4(WUP + s, { EMIT_R(ivp[0]) }, { EMIT_R(ivp[1]) },
                               { EMIT_R(ivp[2]) }, { EMIT_R(ivp[3]) })
            }
        }
    } else if (chunk == 0) {
        { CORE0(0) EMIT_R(s_inv2[0]) }
        { CORE0(1) EMIT_R(s_inv2[1]) }
#pragma unroll 8
        for (int s = 2; s < CLEN; s += 2) {
            const unsigned long long* ivp = &s_inv2[s];
            CORE2(s, { EMIT_R(ivp[0]) }, { EMIT_R(ivp[1]) })
        }
    } else {  // chunk 1: warm covers t = 0..127 incl. the two zero-trigram steps
        { CORE0(0) }
        { CORE0(1) }
#pragma unroll 8
        for (int w = 2; w < WUP; w += 2) { CORE2(w, {}, {}) }
#pragma unroll 8
        for (int s = 0; s < CLEN; s += 2) {
            const unsigned long long* ivp = &s_inv2[s];
            CORE2(WUP + s, { EMIT_R(ivp[0]) }, { EMIT_R(ivp[1]) })
        }
    }
#undef LSTEP
#undef EMIT_D
#undef EMIT_R
#undef CORE4
#undef CORE2
#undef CORE0
}

extern "C" void kernel_launch(void* const* d_in, const int* in_sizes, int n_in,
                              void* d_out, int out_size)
{
    const float* cb  = (const float*)d_in[0];   // (256, 4096) f32 bipolar
    const int*   idx = (const int*)d_in[1];     // (8, 2048) i32
    float*       out = (float*)d_out;           // (8, 2048, 4096) f32

    dim3 pgrid(256, 4);
    pack_kernel<<<pgrid, NTHREADS>>>(cb);

    dim3 grid(NDG, NCHUNK, NB);                 // 8 x 16 x 8 = 1024 blocks
    scan_kernel<<<grid, NTHREADS>>>(idx, out);
}

// round 14
// speedup vs baseline: 1.4821x; 1.4821x over previous
#include <cuda_runtime.h>
#include <cstdint>
#include <cmath>

// HDCProcessor: bit-domain exponential-decay scan, single fused kernel.
// R14: R11 core, but 256 threads x 2 dims/thread (was 128 x 4): same blocks,
//      2x warps/SM (occ 33% -> ~66-86%) to cover the f-LDS -> LUT-LDS -> FFMA2
//      latency chain. LUT formula unchanged; stores are coalesced STG.64.
//   hdc[t,d] = 0.3*s(t,d) + 0.7*s(t,d)*s(t-1,d-1)*s(t-2,d-2)  (signs, rolls mod D)
//   acc_t = 0.95*acc_{t-1} + hdc_t ;  out[t] = acc_t * (1-g)/(1-g^{t+1})
// c in {+-1.0, +-0.4}: smem LUT[f1 f0 y1 y0] = {c_j, c_j+1}, broadcast LDS.
// Chunks 0,1 exact (start at t=0); chunks >=2 use a 128-step warmup
// (truncation ~3.5e-4 rel, measured in R11; gate 1e-3).

#define DDIM     4096
#define NB       8
#define NT       2048
#define NCHUNK   16
#define CLEN     128
#define WUP      128
#define NTHREADS 256               // 2 dims per thread
#define NDG      8                 // 4096 dims / (256 thr * 2 dims)
#define ROWW     17                // words per staged row: 1 halo + 16 slice
#define RWORDS   (256 * ROWW)      // 4352
#define ROWB     (ROWW * 4)
#define SIDXN    (CLEN + WUP + 2)  // 258

__device__ uint32_t g_bitsx[NDG * RWORDS];   // per-dg pre-halo'd packed rows
__device__ float    g_inv[NT];               // (1-g)/(1-g^{t+1})

// ---- packed f32x2 helpers ----
__device__ __forceinline__ unsigned long long pk2(uint32_t lo, uint32_t hi) {
    unsigned long long r;
    asm("mov.b64 %0, {%1, %2};" : "=l"(r) : "r"(lo), "r"(hi));
    return r;
}
#define FMA2(d, a, b, c) \
    asm("fma.rn.f32x2 %0, %1, %2, %3;" : "=l"(d) : "l"(a), "l"(b), "l"(c))
#define MUL2(d, a, b) \
    asm("mul.rn.f32x2 %0, %1, %2;" : "=l"(d) : "l"(a), "l"(b))
#define G2    0x3F7333333F733333ull   // {0.95f, 0.95f}
#define INV05 0x3D4CCCCD3D4CCCCDull   // {0.05f, 0.05f}

// ---- pack: sign bits of the bipolar codebook, expanded per d-group ----
__global__ void pack_kernel(const float* __restrict__ cb) {
    const int row  = blockIdx.x;
    const int lane = threadIdx.x & 31;
    const int wq   = (blockIdx.y << 2) + (threadIdx.x >> 5);  // word quarter 0..15
    for (int k = 0; k < 8; k++) {
        int gw = wq * 8 + k;
        float v = cb[row * DDIM + gw * 32 + lane];
        unsigned m = __ballot_sync(0xffffffffu, v < 0.0f);
        if (lane == 0) {
            g_bitsx[(gw >> 4) * RWORDS + row * ROWW + (gw & 15) + 1] = m;
            int gwn = (gw + 1) & 127;               // this word is the halo of
            if ((gwn & 15) == 0)                    // the next d-group (mod wrap)
                g_bitsx[(gwn >> 4) * RWORDS + row * ROWW] = m;
        }
    }
    if (blockIdx.y == 0) {
        int gid = blockIdx.x * 128 + threadIdx.x;
        if (gid < NT)
            g_inv[gid] = (float)(0.05 / (1.0 - pow(0.95, (double)(gid + 1))));
    }
}

// ---- fused scan ----
__global__ void __launch_bounds__(NTHREADS)
scan_kernel(const int* __restrict__ idx, float* __restrict__ out)
{
    const int dg    = blockIdx.x;
    const int chunk = blockIdx.y;
    const int b     = blockIdx.z;
    const int t0    = chunk * CLEN;
    const int tid   = threadIdx.x;

    __shared__ uint32_t s_bits[RWORDS + 4];
    __shared__ int      s_idx[SIDXN + 2];                // row byte offsets
    __shared__ unsigned long long s_inv2[CLEN];          // packed {inv, inv}
    __shared__ unsigned long long s_lut[16];             // packed {c_j, c_j+1}

    // c LUT: index [f1 f0 y1 y0]; c = 0.3*(f?-1:+1) + 0.7*(y?-1:+1)
    if (tid < 16) {
        float c0 = ((tid & 4) ? -0.3f : 0.3f) + ((tid & 1) ? -0.7f : 0.7f);
        float c1 = ((tid & 8) ? -0.3f : 0.3f) + ((tid & 2) ? -0.7f : 0.7f);
        s_lut[tid] = pk2(__float_as_uint(c0), __float_as_uint(c1));
    }
    // stage packed codebook slice (contiguous uint4 copy, L2-resident source)
    {
        const uint4* src = (const uint4*)(g_bitsx + dg * RWORDS);
        uint4*       dst = (uint4*)s_bits;
        for (int k = tid; k < RWORDS / 4; k += NTHREADS) dst[k] = src[k];
    }
    const int nwarm = chunk ? WUP : 0;     // WUP == CLEN: uniform for chunks >= 1
    const int ts    = t0 - nwarm;          // first scanned timestep
    for (int k = tid; k < SIDXN; k += NTHREADS) {
        int t = ts - 2 + k;                // tail entries past nsteps are unused
        s_idx[k] = ((t >= 0 && t < NT) ? idx[b * NT + t] : 0) * ROWB;
    }
    if (chunk < 3 && tid < CLEN) {         // chunks >= 3: inv == 0.05f exactly
        float v = g_inv[t0 + tid];
        s_inv2[tid] = pk2(__float_as_uint(v), __float_as_uint(v));
    }
    __syncthreads();

    // bit field: global dim (dg*512 + m) lives at staged-row bit (32 + m);
    // this thread handles dims m = 2*tid, 2*tid+1 => needs bits d-2..d+1
    // starting at p = 30 + 2*tid. Both f (cur) and Y (trigram) carry dim j's
    // sign at bit (2+j), so the R11 LUT index formula is unchanged.
    const int p   = 30 + 2 * tid;
    const int q   = p >> 5;
    const int rsh = p & 31;
    const char* bbase = (const char*)(s_bits + q);
    const char* lutb  = (const char*)s_lut;

    uint32_t h1s = 0, h2s = 0;   // histories pre-shifted: f_{t-1}<<1, f_{t-2}<<2
    if (ts >= 2) {               // real history (chunk >= 2)
        const uint32_t* w1 = (const uint32_t*)(bbase + s_idx[1]);
        const uint32_t* w2 = (const uint32_t*)(bbase + s_idx[0]);
        h1s = __funnelshift_r(w1[0], w1[1], rsh) << 1;
        h2s = __funnelshift_r(w2[0], w2[1], rsh) << 2;
    }

    unsigned long long a01 = 0ull;               // packed fp32 accumulator (2 dims)
    float* op = out + ((size_t)b * NT + t0) * DDIM + dg * 512 + 2 * tid;

    // one LUT step body (f given), updates acc only
#define LSTEP(F, H1, H2)                                                      \
        const uint32_t Y_ = (F) ^ (H1) ^ (H2);                                \
        const uint32_t o01_ = (((F) & 12u) | ((Y_ >> 2) & 3u)) << 3;          \
        FMA2(a01, a01, G2, *(const unsigned long long*)(lutb + o01_));

#define EMITV(IV)                                                             \
        unsigned long long o01v;                                              \
        MUL2(o01v, a01, (IV));                                                \
        asm volatile("st.global.b64 [%0], %1;"                                \
                     :: "l"(op), "l"(o01v) : "memory");                       \
        op += DDIM;

    // paired core: sp even; E0/E1 run after each step's acc update
#define CORE2(sp, E0, E1)                                                     \
    {                                                                         \
        const int2 ofs = *(const int2*)(s_idx + (sp));                        \
        const uint32_t* wpA = (const uint32_t*)(bbase + ofs.x);               \
        const uint32_t fA = __funnelshift_r(wpA[0], wpA[1], rsh);             \
        const uint32_t* wpB = (const uint32_t*)(bbase + ofs.y);               \
        const uint32_t fB = __funnelshift_r(wpB[0], wpB[1], rsh);             \
        { LSTEP(fA, h1s, h2s) }                                               \
        E0                                                                    \
        { LSTEP(fB, fA << 1, h1s << 1) }                                      \
        E1                                                                    \
        h2s = fA << 2;                                                        \
        h1s = fB << 1;                                                        \
    }

    // u-only single step for t = 0,1 (reference zeroes shifted-history rows)
#define CORE0(sp)                                                             \
    {                                                                         \
        const uint32_t* wp = (const uint32_t*)(bbase + s_idx[(sp)]);          \
        const uint32_t f = __funnelshift_r(wp[0], wp[1], rsh);                \
        const uint32_t u0 = ((f << 29) & 0x80000000u) | 0x3E99999Au;          \
        const uint32_t u1 = ((f << 28) & 0x80000000u) | 0x3E99999Au;          \
        FMA2(a01, a01, G2, pk2(u0, u1));                                      \
        h2s = h1s << 1;                                                       \
        h1s = f << 1;                                                         \
    }

    if (chunk == 0) {
        { CORE0(2) EMITV(s_inv2[0]) }
        { CORE0(3) EMITV(s_inv2[1]) }
#pragma unroll 8
        for (int s = 2; s < CLEN; s += 2) {
            const unsigned long long* ivp = &s_inv2[s];
            CORE2(s + 2, { EMITV(ivp[0]) }, { EMITV(ivp[1]) })
        }
    } else {
        // ---- warmup: 128 store-free steps ----
        int w = 0;
        if (chunk == 1) { CORE0(2) CORE0(3) w = 2; }
#pragma unroll 8
        for (; w < WUP; w += 2) { CORE2(w + 2, {}, {}) }
        // ---- store phase ----
        if (chunk < 3) {
#pragma unroll 8
            for (int s = 0; s < CLEN; s += 2) {
                const unsigned long long* ivp = &s_inv2[s];
                CORE2(WUP + s + 2, { EMITV(ivp[0]) }, { EMITV(ivp[1]) })
            }
        } else {       // t >= 384: (1-g)/(1-g^(t+1)) == 0.05f exactly in fp32
#pragma unroll 8
            for (int s = 0; s < CLEN; s += 2) {
                CORE2(WUP + s + 2, { EMITV(INV05) }, { EMITV(INV05) })
            }
        }
    }
#undef LSTEP
#undef EMITV
#undef CORE2
#undef CORE0
}

extern "C" void kernel_launch(void* const* d_in, const int* in_sizes, int n_in,
                              void* d_out, int out_size)
{
    const float* cb  = (const float*)d_in[0];   // (256, 4096) f32 bipolar
    const int*   idx = (const int*)d_in[1];     // (8, 2048) i32
    float*       out = (float*)d_out;           // (8, 2048, 4096) f32

    dim3 pgrid(256, 4);
    pack_kernel<<<pgrid, 128>>>(cb);

    dim3 grid(NDG, NCHUNK, NB);                 // 8 x 16 x 8 = 1024 blocks
    scan_kernel<<<grid, NTHREADS>>>(idx, out);
}